// round 5
// baseline (speedup 1.0000x reference)
#include <cuda_runtime.h>
#include <cstddef>

#define TSTEPS 512
#define BATCH  512
#define NUDIM  64
#define NXDIM  128
#define NVDIM  256
#define NYDIM  64
#define RPC    4
#define NCTA   128
#define NTHR   512

// ---------------- packed transposed weights (built once per launch) ----------
// W4[k4 * J + j].q = W[j][4*k4 + q]   (J outputs, K contraction)
__device__ float4 g_C1T4 [32 * NVDIM];
__device__ float4 g_D12T4[16 * NVDIM];
__device__ float4 g_D22T4[16 * NYDIM];
__device__ float4 g_AT4  [32 * NXDIM];
__device__ float4 g_B1T4 [64 * NXDIM];
__device__ float4 g_B2T4 [16 * NXDIM];
__device__ float4 g_C2T4 [32 * NYDIM];
__device__ float4 g_D21T4[64 * NYDIM];
__device__ float4 g_D11P [64 * NVDIM];      // packed D11[j][k] over k (off-diag)
__device__ float  g_D11T [NVDIM * NVDIM];   // scalar D11T[k*256+j] = D11[j][k]

__global__ void prep_kernel(const float* __restrict__ A,  const float* __restrict__ B1,
                            const float* __restrict__ B2, const float* __restrict__ C1,
                            const float* __restrict__ C2, const float* __restrict__ D11,
                            const float* __restrict__ D12,const float* __restrict__ D21,
                            const float* __restrict__ D22)
{
    int id = blockIdx.x * blockDim.x + threadIdx.x;
    int off = 0;
#define XP4(dst, src, J, K)                                                  \
    if (id < off + (J) * (K) / 4) {                                          \
        int i = id - off; int k4 = i / (J); int j = i % (J);                 \
        const float* p = (src) + (size_t)j * (K) + 4 * k4;                   \
        dst[i] = make_float4(p[0], p[1], p[2], p[3]); return;                \
    } off += (J) * (K) / 4;
    XP4(g_C1T4,  C1,  NVDIM, NXDIM)
    XP4(g_D12T4, D12, NVDIM, NUDIM)
    XP4(g_D22T4, D22, NYDIM, NUDIM)
    XP4(g_AT4,   A,   NXDIM, NXDIM)
    XP4(g_B1T4,  B1,  NXDIM, NVDIM)
    XP4(g_B2T4,  B2,  NXDIM, NUDIM)
    XP4(g_C2T4,  C2,  NYDIM, NXDIM)
    XP4(g_D21T4, D21, NYDIM, NVDIM)
    XP4(g_D11P,  D11, NVDIM, NVDIM)
#undef XP4
    if (id < off + NVDIM * NVDIM) {
        int i = id - off; int k = i / NVDIM; int j = i % NVDIM;
        g_D11T[i] = D11[(size_t)j * NVDIM + k];
    }
}

// ---------------- shared memory ----------------
struct Smem {
    float4 C1T4 [32 * NVDIM];     // 128 KB staged
    float4 D12T4[16 * NVDIM];     //  64 KB staged
    float4 xk[2][NXDIM];          // state, float4 across 4 rows
    float4 w[NVDIM];              // equilibrium solution
    float4 uu[2][NUDIM];          // double-buffered input tile
    float  bblk[32][4];           // panel handoff
    float  diagc[8][4][32];       // packed 8x8 strictly-lower coefs
    union {
        float4 bpartA[2][NVDIM];                       // phase-A partials (8 KB)
        struct { float4 xpart[3][NXDIM]; float4 ypart[7][NYDIM]; } cc; // 13 KB
    } ov;
};

#define FMA4C(a0,a1,a2,a3,c,v) do {                       \
    a0 = fmaf((c), (v).x, a0); a1 = fmaf((c), (v).y, a1); \
    a2 = fmaf((c), (v).z, a2); a3 = fmaf((c), (v).w, a3); } while (0)

// apply 32 w-values of panel 'pb' to this thread's (ba0, ba1) using pcN regs
#define APPLY8(pb) do {                                                     \
    _Pragma("unroll")                                                       \
    for (int g2 = 0; g2 < 8; g2++) {                                        \
        const float2* wp = (const float2*)&s.w[(pb) * 32 + 4 * g2];         \
        float2 w0 = wp[0 + h], w1 = wp[2 + h], w2 = wp[4 + h], w3 = wp[6 + h]; \
        ba0 = fmaf(pcN[g2].x, w0.x, ba0); ba1 = fmaf(pcN[g2].x, w0.y, ba1); \
        ba0 = fmaf(pcN[g2].y, w1.x, ba0); ba1 = fmaf(pcN[g2].y, w1.y, ba1); \
        ba0 = fmaf(pcN[g2].z, w2.x, ba0); ba1 = fmaf(pcN[g2].z, w2.y, ba1); \
        ba0 = fmaf(pcN[g2].w, w3.x, ba0); ba1 = fmaf(pcN[g2].w, w3.y, ba1); \
    } } while (0)

__global__ void __launch_bounds__(NTHR, 1)
ren_kernel(const float* __restrict__ x0, const float* __restrict__ u,
           const float* __restrict__ D11,
           const float* __restrict__ bx, const float* __restrict__ bv,
           const float* __restrict__ by, float* __restrict__ out)
{
    extern __shared__ char smem_raw[];
    Smem& s = *reinterpret_cast<Smem*>(smem_raw);
    const int tid  = threadIdx.x;
    const int lane = tid & 31;
    const int wid  = tid >> 5;
    const int row0 = blockIdx.x * RPC;
    const int j    = tid & 255;   // v-feature owned in phases A/B
    const int h    = tid >> 8;    // row-pair selector / k-split selector
    const int Pj   = j >> 5;      // panel of owned feature

    // ---- one-time staging ----
    for (int i = tid; i < 32 * NVDIM; i += NTHR) s.C1T4[i]  = g_C1T4[i];
    for (int i = tid; i < 16 * NVDIM; i += NTHR) s.D12T4[i] = g_D12T4[i];
    if (tid < 32) {
        int blk = tid >> 2, g = tid & 3;
        int base = blk * 32 + g * 8, idx = 0;
        for (int ii = 1; ii < 8; ii++)
            for (int jj = 0; jj < ii; jj++)
                s.diagc[blk][g][idx++] = D11[(size_t)(base + ii) * NVDIM + (base + jj)];
    }
    for (int i = tid; i < RPC * NXDIM; i += NTHR) {
        int r = i >> 7, k = i & 127;
        ((float*)s.xk[0])[k * 4 + r] = x0[(size_t)(row0 + r) * NXDIM + k];
    }
    const float bvr = bv[j];
    const float bxr = bx[tid & 127];
    const float byr = by[tid & 63];

    float dc[32];
    if (wid < 4) {
#pragma unroll
        for (int q = 0; q < 32; q++)
            dc[q] = g_D11T[(size_t)q * NVDIM + lane];
    }
    float ureg = 0.f;
    if (tid < 256) {
        int r = tid >> 6, k = tid & 63;
        ureg = u[((size_t)0 * BATCH + row0 + r) * NUDIM + k];
    }
    __syncthreads();

    float* yout = out + (size_t)BATCH * NXDIM;
    int cur = 0;

    for (int t = 0; t < TSTEPS; t++) {
        const int ub = t & 1;
        if (tid < 256) {
            int r = tid >> 6, k = tid & 63;
            ((float*)s.uu[ub])[k * 4 + r] = ureg;
            int tn = (t + 1 < TSTEPS) ? t + 1 : t;
            ureg = u[((size_t)tn * BATCH + row0 + r) * NUDIM + k];
        }
        __syncthreads();
        const int nxt = cur ^ 1;
        const float4* xc = s.xk[cur];
        const float4* uc = s.uu[ub];

        // ---- phase A (k-split dedup): each weight loaded once; all 4 rows ----
        float p0 = 0.f, p1 = 0.f, p2 = 0.f, p3 = 0.f;
        if (h == 0) {
#pragma unroll 6
            for (int k4 = 0; k4 < 24; k4++) {
                float4 c = s.C1T4[k4 * NVDIM + j];
                const float4* v = &xc[4 * k4];
                FMA4C(p0, p1, p2, p3, c.x, v[0]);
                FMA4C(p0, p1, p2, p3, c.y, v[1]);
                FMA4C(p0, p1, p2, p3, c.z, v[2]);
                FMA4C(p0, p1, p2, p3, c.w, v[3]);
            }
        } else {
#pragma unroll
            for (int i = 0; i < 8; i++) {
                int k4 = 24 + i;
                float4 c = s.C1T4[k4 * NVDIM + j];
                const float4* v = &xc[4 * k4];
                FMA4C(p0, p1, p2, p3, c.x, v[0]);
                FMA4C(p0, p1, p2, p3, c.y, v[1]);
                FMA4C(p0, p1, p2, p3, c.z, v[2]);
                FMA4C(p0, p1, p2, p3, c.w, v[3]);
            }
#pragma unroll 4
            for (int k4 = 0; k4 < 16; k4++) {
                float4 c = s.D12T4[k4 * NVDIM + j];
                const float4* v = &uc[4 * k4];
                FMA4C(p0, p1, p2, p3, c.x, v[0]);
                FMA4C(p0, p1, p2, p3, c.y, v[1]);
                FMA4C(p0, p1, p2, p3, c.z, v[2]);
                FMA4C(p0, p1, p2, p3, c.w, v[3]);
            }
        }
        s.ov.bpartA[h][j] = make_float4(p0, p1, p2, p3);
        __syncthreads();
        const float* qa = (const float*)&s.ov.bpartA[0][j];
        const float* qb = (const float*)&s.ov.bpartA[1][j];
        float ba0 = bvr + qa[2 * h]     + qb[2 * h];
        float ba1 = bvr + qa[2 * h + 1] + qb[2 * h + 1];

        // ---- phase B: pipelined blocked triangular ReLU equilibrium ----
        // per panel p: owners apply near-update w(p-1), hand off; then solver
        // solves p while everyone later applies far-update w(p-1) + prefetches.
        float4 pcN[8];
        for (int p = 0; p < 8; p++) {
            if (Pj == p) {
                if (p > 0) APPLY8(p - 1);
                *(float2*)&s.bblk[j & 31][2 * h] = make_float2(ba0, ba1);
            }
            __syncthreads();                       // B1: bblk visible

            if (wid < 4) {                         // warp r solves row r
                const int r = wid;
                const int base = p * 32;
                float bval = s.bblk[lane][r];
                float wmine = 0.f;
#pragma unroll
                for (int g = 0; g < 4; g++) {
                    const int q0 = g * 8;
                    float cg[28];
#pragma unroll
                    for (int q = 0; q < 28; q++) cg[q] = s.diagc[p][g][q];
                    float bg[8];
#pragma unroll
                    for (int q = 0; q < 8; q++)
                        bg[q] = __shfl_sync(0xffffffffu, bval, q0 + q);
                    float wloc[8];
#pragma unroll
                    for (int jj = 0; jj < 8; jj++) {   // redundant serial resolve
                        float wj = fmaxf(bg[jj], 0.f);
                        wloc[jj] = wj;
#pragma unroll
                        for (int ii = jj + 1; ii < 8; ii++)
                            bg[ii] = fmaf(cg[ii * (ii - 1) / 2 + jj], wj, bg[ii]);
                    }
                    if ((lane >> 3) == g) wmine = wloc[lane & 7];
                    float a0 = 0.f, a1 = 0.f;          // apply (upper coefs are 0)
                    a0 = fmaf(dc[q0 + 0], wloc[0], a0); a1 = fmaf(dc[q0 + 1], wloc[1], a1);
                    a0 = fmaf(dc[q0 + 2], wloc[2], a0); a1 = fmaf(dc[q0 + 3], wloc[3], a1);
                    a0 = fmaf(dc[q0 + 4], wloc[4], a0); a1 = fmaf(dc[q0 + 5], wloc[5], a1);
                    a0 = fmaf(dc[q0 + 6], wloc[6], a0); a1 = fmaf(dc[q0 + 7], wloc[7], a1);
                    bval += a0 + a1;
                }
                ((float*)&s.w[base + lane])[r] = wmine;
                const int nbase = ((p + 1) & 7) * 32;   // next panel diag cols
#pragma unroll
                for (int q = 0; q < 32; q++)
                    dc[q] = g_D11T[(size_t)(nbase + q) * NVDIM + (nbase + lane)];
            }

            if (Pj > p) {                          // far update + coef prefetch
                if (p > 0) APPLY8(p - 1);
#pragma unroll
                for (int g2 = 0; g2 < 8; g2++)
                    pcN[g2] = g_D11P[(p * 8 + g2) * NVDIM + j];
            }
            __syncthreads();                       // B2: w(p) visible
        }

        // ---- phase C: x1 and y, k-split over thread groups ----
        const int xj = tid & 127, xq = tid >> 7;      // 4 k-chunks
        float xa0, xa1, xa2, xa3;
        xa0 = xa1 = xa2 = xa3 = (xq == 0) ? bxr : 0.f;
#pragma unroll 4
        for (int i = 0; i < 8; i++) {                 // A: 32 k per chunk
            int k4 = xq * 8 + i;
            float4 c = g_AT4[k4 * NXDIM + xj];
            const float4* v = &xc[4 * k4];
            FMA4C(xa0, xa1, xa2, xa3, c.x, v[0]);
            FMA4C(xa0, xa1, xa2, xa3, c.y, v[1]);
            FMA4C(xa0, xa1, xa2, xa3, c.z, v[2]);
            FMA4C(xa0, xa1, xa2, xa3, c.w, v[3]);
        }
#pragma unroll 4
        for (int i = 0; i < 16; i++) {                // B1: 64 k per chunk
            int k4 = xq * 16 + i;
            float4 c = g_B1T4[k4 * NXDIM + xj];
            const float4* v = &s.w[4 * k4];
            FMA4C(xa0, xa1, xa2, xa3, c.x, v[0]);
            FMA4C(xa0, xa1, xa2, xa3, c.y, v[1]);
            FMA4C(xa0, xa1, xa2, xa3, c.z, v[2]);
            FMA4C(xa0, xa1, xa2, xa3, c.w, v[3]);
        }
#pragma unroll
        for (int i = 0; i < 4; i++) {                 // B2: 16 k per chunk
            int k4 = xq * 4 + i;
            float4 c = g_B2T4[k4 * NXDIM + xj];
            const float4* v = &uc[4 * k4];
            FMA4C(xa0, xa1, xa2, xa3, c.x, v[0]);
            FMA4C(xa0, xa1, xa2, xa3, c.y, v[1]);
            FMA4C(xa0, xa1, xa2, xa3, c.z, v[2]);
            FMA4C(xa0, xa1, xa2, xa3, c.w, v[3]);
        }
        if (xq > 0) s.ov.cc.xpart[xq - 1][xj] = make_float4(xa0, xa1, xa2, xa3);

        const int yj = tid & 63, yq = tid >> 6;       // 8 k-chunks
        float ya0, ya1, ya2, ya3;
        ya0 = ya1 = ya2 = ya3 = (yq == 0) ? byr : 0.f;
#pragma unroll
        for (int i = 0; i < 4; i++) {                 // C2: 16 k per chunk
            int k4 = yq * 4 + i;
            float4 c = g_C2T4[k4 * NYDIM + yj];
            const float4* v = &xc[4 * k4];
            FMA4C(ya0, ya1, ya2, ya3, c.x, v[0]);
            FMA4C(ya0, ya1, ya2, ya3, c.y, v[1]);
            FMA4C(ya0, ya1, ya2, ya3, c.z, v[2]);
            FMA4C(ya0, ya1, ya2, ya3, c.w, v[3]);
        }
#pragma unroll 4
        for (int i = 0; i < 8; i++) {                 // D21: 32 k per chunk
            int k4 = yq * 8 + i;
            float4 c = g_D21T4[k4 * NYDIM + yj];
            const float4* v = &s.w[4 * k4];
            FMA4C(ya0, ya1, ya2, ya3, c.x, v[0]);
            FMA4C(ya0, ya1, ya2, ya3, c.y, v[1]);
            FMA4C(ya0, ya1, ya2, ya3, c.z, v[2]);
            FMA4C(ya0, ya1, ya2, ya3, c.w, v[3]);
        }
#pragma unroll
        for (int i = 0; i < 2; i++) {                 // D22: 8 k per chunk
            int k4 = yq * 2 + i;
            float4 c = g_D22T4[k4 * NYDIM + yj];
            const float4* v = &uc[4 * k4];
            FMA4C(ya0, ya1, ya2, ya3, c.x, v[0]);
            FMA4C(ya0, ya1, ya2, ya3, c.y, v[1]);
            FMA4C(ya0, ya1, ya2, ya3, c.z, v[2]);
            FMA4C(ya0, ya1, ya2, ya3, c.w, v[3]);
        }
        if (yq > 0) s.ov.cc.ypart[yq - 1][yj] = make_float4(ya0, ya1, ya2, ya3);
        __syncthreads();

        // ---- combines ----
        if (xq == 0) {
#pragma unroll
            for (int pqq = 0; pqq < 3; pqq++) {
                float4 pp = s.ov.cc.xpart[pqq][xj];
                xa0 += pp.x; xa1 += pp.y; xa2 += pp.z; xa3 += pp.w;
            }
            s.xk[nxt][xj] = make_float4(xa0, xa1, xa2, xa3);
        }
        if (yq == 0) {
#pragma unroll
            for (int pqq = 0; pqq < 7; pqq++) {
                float4 pp = s.ov.cc.ypart[pqq][yj];
                ya0 += pp.x; ya1 += pp.y; ya2 += pp.z; ya3 += pp.w;
            }
            float* yo = yout + ((size_t)t * BATCH + row0) * NYDIM + yj;
            yo[0 * NYDIM] = ya0;
            yo[1 * NYDIM] = ya1;
            yo[2 * NYDIM] = ya2;
            yo[3 * NYDIM] = ya3;
        }
        cur ^= 1;
    }

    // ---- final state x1 ----
    __syncthreads();
    if (tid < NXDIM) {
        float4 v = s.xk[cur][tid];
        out[(size_t)(row0 + 0) * NXDIM + tid] = v.x;
        out[(size_t)(row0 + 1) * NXDIM + tid] = v.y;
        out[(size_t)(row0 + 2) * NXDIM + tid] = v.z;
        out[(size_t)(row0 + 3) * NXDIM + tid] = v.w;
    }
}

extern "C" void kernel_launch(void* const* d_in, const int* in_sizes, int n_in,
                              void* d_out, int out_size)
{
    const float* x0  = (const float*)d_in[0];
    const float* u   = (const float*)d_in[1];
    const float* A   = (const float*)d_in[2];
    const float* B1  = (const float*)d_in[3];
    const float* B2  = (const float*)d_in[4];
    const float* C1  = (const float*)d_in[5];
    const float* C2  = (const float*)d_in[6];
    const float* D11 = (const float*)d_in[7];
    const float* D12 = (const float*)d_in[8];
    const float* D21 = (const float*)d_in[9];
    const float* D22 = (const float*)d_in[10];
    const float* bx  = (const float*)d_in[11];
    const float* bv  = (const float*)d_in[12];
    const float* by  = (const float*)d_in[13];
    float* out = (float*)d_out;

    prep_kernel<<<452, 256>>>(A, B1, B2, C1, C2, D11, D12, D21, D22);

    size_t smem = sizeof(Smem);
    cudaFuncSetAttribute(ren_kernel, cudaFuncAttributeMaxDynamicSharedMemorySize,
                         (int)smem);
    ren_kernel<<<NCTA, NTHR, smem>>>(x0, u, D11, bx, bv, by, out);
}